// round 5
// baseline (speedup 1.0000x reference)
#include <cuda_runtime.h>

// LocalizeAttention gather: out[bh, n, f, :] = x[bh, n + shift_f, :] (zero at edges).
// BH=16, H=W=D=24 (N=13824), d=32 floats, 27 filters.
// R5: SMEM-tiled load (kills 27x read amplification) + warp-per-row write phase:
// each warp owns one output row n (3456 B contiguous) and walks it sequentially
// in 512 B fully-contiguous STG.128 chunks.

#define HH 24
#define WW 24
#define DD 24
#define NN (HH * WW * DD)      // 13824
#define FN 27
#define ROW4 8                 // float4 per feature row (32 floats)
#define JT 2                   // j-rows per block
#define LJ (JT + 2)            // 4 (with halo)
#define LK (DD + 2)            // 26 (with halo)
#define LROWS (3 * LJ * LK)    // 312 source rows in tile
#define THREADS 384            // 12 warps; 48 output rows per block -> 4 rows/warp

__global__ void __launch_bounds__(THREADS)
localize_kernel(const float4* __restrict__ x, float4* __restrict__ out)
{
    __shared__ float4 s[LROWS * ROW4];   // 2496 float4 = 39936 B

    const int bh = blockIdx.z;
    const int i  = blockIdx.y;
    const int j0 = blockIdx.x * JT;
    const int t  = threadIdx.x;

    // ---- Load phase: tile + halo, zeros outside the volume ----
    const float4 zero = make_float4(0.f, 0.f, 0.f, 0.f);
    for (int l4 = t; l4 < LROWS * ROW4; l4 += THREADS) {
        int d4  = l4 & 7;
        int row = l4 >> 3;
        int li  = row / (LJ * LK);
        int r   = row - li * (LJ * LK);
        int lj  = r / LK;
        int lk  = r - lj * LK;
        int ii  = i  + li - 1;
        int jj  = j0 + lj - 1;
        int kk  = lk - 1;
        float4 v = zero;
        if ((unsigned)ii < HH && (unsigned)jj < WW && (unsigned)kk < DD) {
            v = __ldg(&x[((size_t)bh * NN + ii * (WW * DD) + jj * DD + kk) * ROW4 + d4]);
        }
        s[l4] = v;
    }
    __syncthreads();

    // ---- Write phase: warp-per-row, fully contiguous 512 B stores ----
    const int lane = t & 31;
    const int w    = t >> 5;            // 0..11

    #pragma unroll
    for (int q = 0; q < 4; q++) {
        const int nn = w * 4 + q;       // 0..47 local output row
        const int jl = nn / DD;
        const int k  = nn - jl * DD;
        const int n  = i * (WW * DD) + (j0 + jl) * DD + k;

        float4* dst = out + ((size_t)bh * NN + n) * (FN * ROW4);
        const float4* sp = s + (jl * LK + k) * ROW4;   // tile row (fi=fj=fk=0 base)

        #pragma unroll
        for (int it = 0; it < 7; it++) {
            const int idx = it * 32 + lane;             // 0..223, valid < 216
            if (idx < FN * ROW4) {
                int f  = idx >> 3;
                int d4 = idx & 7;
                int fi = f / 9;
                int r  = f - fi * 9;
                int fj = r / 3;
                int fk = r - fj * 3;
                int soff = ((fi * LJ + fj) * LK + fk) * ROW4;
                __stcs(dst + idx, sp[soff + d4]);
            }
        }
    }
}

extern "C" void kernel_launch(void* const* d_in, const int* in_sizes, int n_in,
                              void* d_out, int out_size)
{
    const float4* x = (const float4*)d_in[0];
    float4* out = (float4*)d_out;

    int BH = out_size / (NN * FN * 32);     // batch*heads (16 for reference shapes)
    dim3 grid(WW / JT, HH, BH);
    localize_kernel<<<grid, THREADS>>>(x, out);
}

// round 7
// speedup vs baseline: 1.0225x; 1.0225x over previous
#include <cuda_runtime.h>

// LocalizeAttention gather: out[bh, n, f, :] = x[bh, n + shift_f, :] (zero at edges).
// BH=16, H=W=D=24 (N=13824), d=32 floats, 27 filters.
// R6: same SMEM-tiled design as R4, retiled JT=3 so grid=3072 with 3 blocks/SM
// (444 concurrent) -> 6.92 waves, last wave 92% full (was 6.23 waves, 23% tail).

#define HH 24
#define WW 24
#define DD 24
#define NN (HH * WW * DD)      // 13824
#define FN 27
#define ROW4 8                 // float4 per feature row (32 floats)
#define JT 3                   // j-rows per block
#define LJ (JT + 2)            // 5 (with halo)
#define LK (DD + 2)            // 26 (with halo)
#define LROWS (3 * LJ * LK)    // 390 source rows in tile
#define THREADS 576            // = JT*DD*8 write lanes

__global__ void __launch_bounds__(THREADS, 3)
localize_kernel(const float4* __restrict__ x, float4* __restrict__ out)
{
    __shared__ float4 s[LROWS * ROW4];   // 3120 float4 = 49920 B

    const int bh = blockIdx.z;
    const int i  = blockIdx.y;
    const int j0 = blockIdx.x * JT;
    const int t  = threadIdx.x;

    // ---- Load phase: tile + halo, zeros outside the volume ----
    const float4 zero = make_float4(0.f, 0.f, 0.f, 0.f);
    for (int l4 = t; l4 < LROWS * ROW4; l4 += THREADS) {
        int d4  = l4 & 7;
        int row = l4 >> 3;
        int li  = row / (LJ * LK);
        int r   = row - li * (LJ * LK);
        int lj  = r / LK;
        int lk  = r - lj * LK;
        int ii  = i  + li - 1;
        int jj  = j0 + lj - 1;
        int kk  = lk - 1;
        float4 v = zero;
        if ((unsigned)ii < HH && (unsigned)jj < WW && (unsigned)kk < DD) {
            v = __ldg(&x[((size_t)bh * NN + ii * (WW * DD) + jj * DD + kk) * ROW4 + d4]);
        }
        s[l4] = v;
    }
    __syncthreads();

    // ---- Write phase: one thread per (jl, k, d4); 27 SMEM reads + 27 streaming stores ----
    const int d4 = t & 7;
    const int nl = t >> 3;          // 0..71
    const int jl = nl / DD;         // 0..2
    const int k  = nl - jl * DD;    // 0..23

    const int n = i * (WW * DD) + (j0 + jl) * DD + k;
    float4* dst = out + ((size_t)bh * NN + n) * (FN * ROW4) + d4;
    const float4* sp = s + ((size_t)jl * LK + k) * ROW4 + d4;

    #pragma unroll
    for (int fi = 0; fi < 3; fi++) {
        #pragma unroll
        for (int fj = 0; fj < 3; fj++) {
            #pragma unroll
            for (int fk = 0; fk < 3; fk++) {
                const int soff = ((fi * LJ + fj) * LK + fk) * ROW4;
                __stcs(dst + ((fi * 3 + fj) * 3 + fk) * ROW4, sp[soff]);
            }
        }
    }
}

extern "C" void kernel_launch(void* const* d_in, const int* in_sizes, int n_in,
                              void* d_out, int out_size)
{
    const float4* x = (const float4*)d_in[0];
    float4* out = (float4*)d_out;

    int BH = out_size / (NN * FN * 32);     // batch*heads (16 for reference shapes)
    dim3 grid(WW / JT, HH, BH);
    localize_kernel<<<grid, THREADS>>>(x, out);
}